// round 6
// baseline (speedup 1.0000x reference)
#include <cuda_runtime.h>
#include <cstdint>
#include <cstddef>

#define BB   32
#define SS   1024
#define HH   256
#define G4   1024          // 4*H
#define HST  260           // h_sh row stride (floats), 16B-aligned

#define HN_OFF (32ull*1024ull*512ull)            // 16777216
#define CN_OFF (HN_OFF + 2ull*32ull*512ull)      // +32768

// ---------------- device scratch (no cudaMalloc allowed) ----------------
__device__ float g_xproj[2][SS*BB][G4];   // [dir][s*32+b][gate]  268MB
__device__ float g_out0[SS*BB][512];      // layer0 output [s*32+b][ch]

// ---------------- helpers ------------------------------------------------
__device__ __forceinline__ void fma2(unsigned long long &d,
                                     unsigned long long a,
                                     unsigned long long b) {
    asm("fma.rn.f32x2 %0, %1, %2, %0;" : "+l"(d) : "l"(a), "l"(b));
}
__device__ __forceinline__ float hsum2(unsigned long long v) {
    return __uint_as_float((unsigned)v) + __uint_as_float((unsigned)(v >> 32));
}
__device__ __forceinline__ float sigf(float x) { return 1.f / (1.f + expf(-x)); }

__device__ __forceinline__ uint32_t smem_u32(const void* p) {
    return (uint32_t)__cvta_generic_to_shared(p);
}
__device__ __forceinline__ void st_cluster_f32(uint32_t laddr, uint32_t rk, float v) {
    uint32_t ra;
    asm volatile("mapa.shared::cluster.u32 %0, %1, %2;"
                 : "=r"(ra) : "r"(laddr), "r"(rk));
    asm volatile("st.shared::cluster.f32 [%0], %1;"
                 :: "r"(ra), "f"(v) : "memory");
}

// ---------------- input projection GEMM (double-buffered) ----------------
// out[dir][m][g] = sum_k X(m,k) * W_dir[g][k] + bih[g] + bhh[g]
// BM=128, BN=64, BK=16, 256 threads, 8x4 per thread, 2-stage smem pipeline.
__global__ void __launch_bounds__(256, 2) xproj_kernel(
    const float* __restrict__ xin, int layer, int K,
    const float* __restrict__ Wf, const float* __restrict__ Wb,
    const float* __restrict__ bihf, const float* __restrict__ bhhf,
    const float* __restrict__ bihb, const float* __restrict__ bhhb)
{
    __shared__ float As[2][16][128];
    __shared__ float Bs[2][16][64];
    const int dir = blockIdx.z;
    const float* W  = dir ? Wb   : Wf;
    const float* bi = dir ? bihb : bihf;
    const float* bh = dir ? bhhb : bhhf;
    const float* X  = (layer == 0) ? xin : &g_out0[0][0];
    const int m0 = blockIdx.y * 128;
    const int n0 = blockIdx.x * 64;
    const int tid = threadIdx.x;
    const int ty = tid >> 4, tx = tid & 15;
    const int nIt = K >> 4;

    // per-thread staging addresses
    int rowA[2], kkA[2];
    const float* apB[2];
    #pragma unroll
    for (int jj = 0; jj < 2; jj++) {
        int idx = tid * 2 + jj;
        rowA[jj] = idx >> 2;
        kkA[jj]  = (idx & 3) << 2;
        int m = m0 + rowA[jj];
        if (layer == 0) {
            int s = m >> 5, b = m & 31;
            apB[jj] = X + ((size_t)b * SS + s) * 256 + kkA[jj];
        } else {
            apB[jj] = X + (size_t)m * 512 + kkA[jj];
        }
    }
    const int nB = tid >> 2, kkB = (tid & 3) << 2;
    const float* bpB = W + (size_t)(n0 + nB) * K + kkB;

    float acc[8][4];
    #pragma unroll
    for (int i = 0; i < 8; i++)
        #pragma unroll
        for (int j = 0; j < 4; j++) acc[i][j] = 0.f;

    // prologue: stage tile 0 into buffer 0
    float4 aR0 = *(const float4*)apB[0];
    float4 aR1 = *(const float4*)apB[1];
    float4 bR  = *(const float4*)bpB;
    As[0][kkA[0]+0][rowA[0]] = aR0.x; As[0][kkA[0]+1][rowA[0]] = aR0.y;
    As[0][kkA[0]+2][rowA[0]] = aR0.z; As[0][kkA[0]+3][rowA[0]] = aR0.w;
    As[0][kkA[1]+0][rowA[1]] = aR1.x; As[0][kkA[1]+1][rowA[1]] = aR1.y;
    As[0][kkA[1]+2][rowA[1]] = aR1.z; As[0][kkA[1]+3][rowA[1]] = aR1.w;
    Bs[0][kkB+0][nB] = bR.x; Bs[0][kkB+1][nB] = bR.y;
    Bs[0][kkB+2][nB] = bR.z; Bs[0][kkB+3][nB] = bR.w;
    __syncthreads();

    for (int it = 0; it < nIt; it++) {
        const int cur = it & 1;
        const bool more = (it + 1 < nIt);
        if (more) {
            int k0n = (it + 1) << 4;
            aR0 = *(const float4*)(apB[0] + k0n);
            aR1 = *(const float4*)(apB[1] + k0n);
            bR  = *(const float4*)(bpB + k0n);
        }
        #pragma unroll
        for (int kk = 0; kk < 16; kk++) {
            float4 a0 = *(const float4*)&As[cur][kk][ty * 8];
            float4 a1 = *(const float4*)&As[cur][kk][ty * 8 + 4];
            float4 bv = *(const float4*)&Bs[cur][kk][tx * 4];
            float ar[8] = {a0.x, a0.y, a0.z, a0.w, a1.x, a1.y, a1.z, a1.w};
            float br[4] = {bv.x, bv.y, bv.z, bv.w};
            #pragma unroll
            for (int i = 0; i < 8; i++)
                #pragma unroll
                for (int j = 0; j < 4; j++)
                    acc[i][j] += ar[i] * br[j];
        }
        if (more) {
            const int nxt = cur ^ 1;
            As[nxt][kkA[0]+0][rowA[0]] = aR0.x; As[nxt][kkA[0]+1][rowA[0]] = aR0.y;
            As[nxt][kkA[0]+2][rowA[0]] = aR0.z; As[nxt][kkA[0]+3][rowA[0]] = aR0.w;
            As[nxt][kkA[1]+0][rowA[1]] = aR1.x; As[nxt][kkA[1]+1][rowA[1]] = aR1.y;
            As[nxt][kkA[1]+2][rowA[1]] = aR1.z; As[nxt][kkA[1]+3][rowA[1]] = aR1.w;
            Bs[nxt][kkB+0][nB] = bR.x; Bs[nxt][kkB+1][nB] = bR.y;
            Bs[nxt][kkB+2][nB] = bR.z; Bs[nxt][kkB+3][nB] = bR.w;
        }
        __syncthreads();
    }

    float bsv[4];
    #pragma unroll
    for (int j = 0; j < 4; j++) {
        int c = n0 + tx * 4 + j;
        bsv[j] = bi[c] + bh[c];
    }
    #pragma unroll
    for (int i = 0; i < 8; i++) {
        int m = m0 + ty * 8 + i;
        float4 o;
        o.x = acc[i][0] + bsv[0]; o.y = acc[i][1] + bsv[1];
        o.z = acc[i][2] + bsv[2]; o.w = acc[i][3] + bsv[3];
        *(float4*)&g_xproj[dir][m][n0 + tx * 4] = o;
    }
}

// ---------------- cluster-parallel recurrent kernel ----------------------
// 16 clusters x 8 CTAs; cluster = (dir, batch group of 4); CTA rank owns
// h-indices [32r,32r+32) for all 4 gates. Whh slice lives in REGISTERS
// (thread = (gate, k-half, j-lane) holds 64 f32x2). h is read from smem via
// warp-uniform broadcast loads. One cluster barrier per step.
__global__ void __launch_bounds__(256, 1) __cluster_dims__(8, 1, 1)
rec_kernel(int layer,
           const float* __restrict__ Whf, const float* __restrict__ Whb,
           const float* __restrict__ mask, float* __restrict__ dout)
{
    __shared__ float h_sh[2][4][HST];   // [buf][batch][k]
    __shared__ float part[128][9];      // [gate*32+jl][b*2+kh], pad 9

    const int bx   = blockIdx.x;
    const int cid  = bx >> 3;
    const int rank = bx & 7;
    const int dir  = cid & 1;
    const int bg4  = (cid >> 1) * 4;
    const int tid  = threadIdx.x;
    const float* Whh = dir ? Whb : Whf;

    // thread role in dot: gate gq, k-half kh, j-lane jl
    const int gq = tid >> 6;
    const int kh = (tid >> 5) & 1;
    const int jl = tid & 31;
    const int growDot = gq * 256 + rank * 32 + jl;

    // Whh slice -> registers: 64 packed f32x2 over k = kh*128 .. kh*128+127
    unsigned long long w[64];
    {
        const ulonglong2* wp =
            (const ulonglong2*)&Whh[(size_t)growDot * 256 + kh * 128];
        #pragma unroll
        for (int i = 0; i < 32; i++) {
            ulonglong2 v = wp[i];
            w[2 * i]     = v.x;
            w[2 * i + 1] = v.y;
        }
    }

    // update role (tid < 128): batch ub, j-lane ujl
    const int ub  = tid >> 5;
    const int ujl = tid & 31;
    const int bglobal = bg4 + ub;
    const int jglob = rank * 32 + ujl;
    float c_reg = 0.f;

    // zero h buffer 0
    for (int i = tid; i < 4 * HST; i += 256) (&h_sh[0][0][0])[i] = 0.f;

    // prefetch step-0 xproj + mask
    float xp[4]; float mt = 0.f;
    if (tid < 128) {
        const int s0 = dir ? (SS - 1) : 0;
        const float* xb = &g_xproj[dir][(size_t)(s0 * 32 + bglobal)][jglob];
        #pragma unroll
        for (int g = 0; g < 4; g++) xp[g] = __ldcs(xb + g * 256);
        mt = mask[bglobal * SS + s0];
    }
    __syncthreads();

    int p = 0;
    for (int t = 0; t < SS; t++) {
        const int s = dir ? (SS - 1 - t) : t;
        const float (*hb)[HST] = h_sh[p];

        // dot over this thread's k-half; h loads are warp-uniform broadcasts
        unsigned long long a0 = 0ull, a1 = 0ull, a2 = 0ull, a3 = 0ull;
        #pragma unroll
        for (int i = 0; i < 32; i++) {
            const int kk = kh * 128 + i * 4;
            ulonglong2 h0 = *(const ulonglong2*)&hb[0][kk];
            ulonglong2 h1 = *(const ulonglong2*)&hb[1][kk];
            ulonglong2 h2 = *(const ulonglong2*)&hb[2][kk];
            ulonglong2 h3 = *(const ulonglong2*)&hb[3][kk];
            fma2(a0, h0.x, w[2*i]); fma2(a0, h0.y, w[2*i+1]);
            fma2(a1, h1.x, w[2*i]); fma2(a1, h1.y, w[2*i+1]);
            fma2(a2, h2.x, w[2*i]); fma2(a2, h2.y, w[2*i+1]);
            fma2(a3, h3.x, w[2*i]); fma2(a3, h3.y, w[2*i+1]);
        }
        {
            const int row = gq * 32 + jl;
            part[row][0 * 2 + kh] = hsum2(a0);
            part[row][1 * 2 + kh] = hsum2(a1);
            part[row][2 * 2 + kh] = hsum2(a2);
            part[row][3 * 2 + kh] = hsum2(a3);
        }
        __syncthreads();

        // gate combine + state update + DSMEM h push
        if (tid < 128) {
            float gv[4];
            #pragma unroll
            for (int g = 0; g < 4; g++) {
                const int row = g * 32 + ujl;
                gv[g] = xp[g] + part[row][ub * 2] + part[row][ub * 2 + 1];
            }
            float iv = sigf(gv[0]);
            float fv = sigf(gv[1]);
            float gg = tanhf(gv[2]);
            float ov = sigf(gv[3]);
            float c = (fv * c_reg + iv * gg) * mt;     // c0 = 0
            float h = ov * tanhf(c) * mt;              // h0 = 0
            c_reg = c;

            // push h into next buffer of all 8 CTAs (incl. self)
            uint32_t laddr = smem_u32(&h_sh[p ^ 1][ub][jglob]);
            #pragma unroll
            for (int rk = 0; rk < 8; rk++) st_cluster_f32(laddr, rk, h);

            // sequence output
            if (layer == 0)
                g_out0[s * 32 + bglobal][dir * 256 + jglob] = h;
            else
                dout[((size_t)bglobal * SS + s) * 512 + dir * 256 + jglob] = h;
            if (t == SS - 1) {
                size_t off = (size_t)layer * BB * 512 + (size_t)bglobal * 512
                           + dir * 256 + jglob;
                dout[HN_OFF + off] = h;
                dout[CN_OFF + off] = c;
            }

            // prefetch next step's xproj + mask
            if (t + 1 < SS) {
                const int sn = dir ? (SS - 2 - t) : (t + 1);
                const float* xb = &g_xproj[dir][(size_t)(sn * 32 + bglobal)][jglob];
                #pragma unroll
                for (int g = 0; g < 4; g++) xp[g] = __ldcs(xb + g * 256);
                mt = mask[bglobal * SS + sn];
            }
        }

        // cluster barrier: release DSMEM pushes, acquire peers' pushes
        asm volatile("barrier.cluster.arrive.aligned;" ::: "memory");
        asm volatile("barrier.cluster.wait.aligned;"   ::: "memory");
        p ^= 1;
    }
}

// ---------------- launch ------------------------------------------------
extern "C" void kernel_launch(void* const* d_in, const int* in_sizes, int n_in,
                              void* d_out, int out_size)
{
    const float* inputs  = (const float*)d_in[0];
    const float* mask    = (const float*)d_in[1];
    const float* l0f_Wih = (const float*)d_in[2];
    const float* l0f_Whh = (const float*)d_in[3];
    const float* l0f_bih = (const float*)d_in[4];
    const float* l0f_bhh = (const float*)d_in[5];
    const float* l0b_Wih = (const float*)d_in[6];
    const float* l0b_Whh = (const float*)d_in[7];
    const float* l0b_bih = (const float*)d_in[8];
    const float* l0b_bhh = (const float*)d_in[9];
    const float* l1f_Wih = (const float*)d_in[10];
    const float* l1f_Whh = (const float*)d_in[11];
    const float* l1f_bih = (const float*)d_in[12];
    const float* l1f_bhh = (const float*)d_in[13];
    const float* l1b_Wih = (const float*)d_in[14];
    const float* l1b_Whh = (const float*)d_in[15];
    const float* l1b_bih = (const float*)d_in[16];
    const float* l1b_bhh = (const float*)d_in[17];
    float* out = (float*)d_out;

    dim3 g(16, 256, 2);   // N/64, M/128, dirs
    xproj_kernel<<<g, 256>>>(inputs, 0, 256,
                             l0f_Wih, l0b_Wih, l0f_bih, l0f_bhh, l0b_bih, l0b_bhh);
    rec_kernel<<<128, 256>>>(0, l0f_Whh, l0b_Whh, mask, out);

    xproj_kernel<<<g, 256>>>(nullptr, 1, 512,
                             l1f_Wih, l1b_Wih, l1f_bih, l1f_bhh, l1b_bih, l1b_bhh);
    rec_kernel<<<128, 256>>>(1, l1f_Whh, l1b_Whh, mask, out);
}

// round 12
// speedup vs baseline: 1.0286x; 1.0286x over previous
#include <cuda_runtime.h>
#include <cstdint>
#include <cstddef>

#define BB   32
#define SS   1024
#define HH   256
#define G4   1024          // 4*H
#define WST  260           // rec w_sh row stride (floats)
#define HST  260           // rec h_sh row stride

#define HN_OFF (32ull*1024ull*512ull)            // 16777216
#define CN_OFF (HN_OFF + 2ull*32ull*512ull)      // +32768

// ---------------- device scratch (no cudaMalloc allowed) ----------------
__device__ float g_xproj[2][SS*BB][G4];   // [dir][s*32+b][gate]  268MB
__device__ float g_out0[SS*BB][512];      // layer0 output [s*32+b][ch]

// ---------------- helpers ------------------------------------------------
__device__ __forceinline__ void fma2(unsigned long long &d,
                                     unsigned long long a,
                                     unsigned long long b) {
    asm("fma.rn.f32x2 %0, %1, %2, %0;" : "+l"(d) : "l"(a), "l"(b));
}
__device__ __forceinline__ float hsum2(unsigned long long v) {
    return __uint_as_float((unsigned)v) + __uint_as_float((unsigned)(v >> 32));
}
__device__ __forceinline__ unsigned long long pack2(float x, float y) {
    unsigned long long r;
    asm("mov.b64 %0, {%1, %2};" : "=l"(r) : "f"(x), "f"(y));
    return r;
}
__device__ __forceinline__ float sigf(float x) { return 1.f / (1.f + expf(-x)); }

__device__ __forceinline__ uint32_t smem_u32(const void* p) {
    return (uint32_t)__cvta_generic_to_shared(p);
}
__device__ __forceinline__ void st_cluster_f32(uint32_t laddr, uint32_t rk, float v) {
    uint32_t ra;
    asm volatile("mapa.shared::cluster.u32 %0, %1, %2;"
                 : "=r"(ra) : "r"(laddr), "r"(rk));
    asm volatile("st.shared::cluster.f32 [%0], %1;"
                 :: "r"(ra), "f"(v) : "memory");
}

// ---------------- input projection GEMM (packed f32x2, k-pair layout) ----
// out[dir][m][g] = sum_k X(m,k) * W_dir[g][k] + bih[g] + bhh[g]
// BM=128, BN=64, BK=16, 256 threads, 8x4 per thread.
// Smem tiles are k-pair packed ull: Ap[kp][m], Bp[kp][n]. Thread's n-set is
// {tx, tx+16, tx+32, tx+48} -> lane-consecutive 64-bit B loads (conflict-
// free); A loads are warp-broadcast. Double-buffered, 2 CTAs/SM.
#define APAD 130   // ull row stride for Ap (>=128), bank-staggered
#define BPAD 66    // ull row stride for Bp (>=64), bank-staggered
__global__ void __launch_bounds__(256, 2) xproj_kernel(
    const float* __restrict__ xin, int layer, int K,
    const float* __restrict__ Wf, const float* __restrict__ Wb,
    const float* __restrict__ bihf, const float* __restrict__ bhhf,
    const float* __restrict__ bihb, const float* __restrict__ bhhb)
{
    __shared__ unsigned long long Ap[2][8][APAD];
    __shared__ unsigned long long Bp[2][8][BPAD];
    const int dir = blockIdx.z;
    const float* W  = dir ? Wb   : Wf;
    const float* bi = dir ? bihb : bihf;
    const float* bh = dir ? bhhb : bhhf;
    const float* X  = (layer == 0) ? xin : &g_out0[0][0];
    const int m0 = blockIdx.y * 128;
    const int n0 = blockIdx.x * 64;
    const int tid = threadIdx.x;
    const int ty = tid >> 4, tx = tid & 15;
    const int nIt = K >> 4;

    // staging roles
    int mA[2], kcA[2];
    const float* apB[2];
    #pragma unroll
    for (int jj = 0; jj < 2; jj++) {
        int idx = tid * 2 + jj;
        mA[jj]  = idx >> 2;
        kcA[jj] = (idx & 3) << 2;        // k offset within tile: 0,4,8,12
        int m = m0 + mA[jj];
        if (layer == 0) {
            int s = m >> 5, b = m & 31;
            apB[jj] = X + ((size_t)b * SS + s) * 256 + kcA[jj];
        } else {
            apB[jj] = X + (size_t)m * 512 + kcA[jj];
        }
    }
    const int nB = tid >> 2, kcB = (tid & 3) << 2;
    const float* bpB = W + (size_t)(n0 + nB) * K + kcB;

    unsigned long long acc[8][4];
    #pragma unroll
    for (int i = 0; i < 8; i++)
        #pragma unroll
        for (int j = 0; j < 4; j++) acc[i][j] = 0ull;

    // prologue: stage tile 0 into buffer 0
    float4 aR0 = *(const float4*)apB[0];
    float4 aR1 = *(const float4*)apB[1];
    float4 bR  = *(const float4*)bpB;
    Ap[0][(kcA[0] >> 1) + 0][mA[0]] = pack2(aR0.x, aR0.y);
    Ap[0][(kcA[0] >> 1) + 1][mA[0]] = pack2(aR0.z, aR0.w);
    Ap[0][(kcA[1] >> 1) + 0][mA[1]] = pack2(aR1.x, aR1.y);
    Ap[0][(kcA[1] >> 1) + 1][mA[1]] = pack2(aR1.z, aR1.w);
    Bp[0][(kcB >> 1) + 0][nB] = pack2(bR.x, bR.y);
    Bp[0][(kcB >> 1) + 1][nB] = pack2(bR.z, bR.w);
    __syncthreads();

    for (int it = 0; it < nIt; it++) {
        const int cur = it & 1;
        const bool more = (it + 1 < nIt);
        if (more) {
            int k0n = (it + 1) << 4;
            aR0 = *(const float4*)(apB[0] + k0n);
            aR1 = *(const float4*)(apB[1] + k0n);
            bR  = *(const float4*)(bpB + k0n);
        }
        #pragma unroll
        for (int kp = 0; kp < 8; kp++) {
            unsigned long long b2[4];
            #pragma unroll
            for (int j = 0; j < 4; j++)
                b2[j] = Bp[cur][kp][tx + 16 * j];
            #pragma unroll
            for (int i = 0; i < 8; i++) {
                unsigned long long a2 = Ap[cur][kp][ty * 8 + i];
                #pragma unroll
                for (int j = 0; j < 4; j++) fma2(acc[i][j], a2, b2[j]);
            }
        }
        if (more) {
            const int nxt = cur ^ 1;
            Ap[nxt][(kcA[0] >> 1) + 0][mA[0]] = pack2(aR0.x, aR0.y);
            Ap[nxt][(kcA[0] >> 1) + 1][mA[0]] = pack2(aR0.z, aR0.w);
            Ap[nxt][(kcA[1] >> 1) + 0][mA[1]] = pack2(aR1.x, aR1.y);
            Ap[nxt][(kcA[1] >> 1) + 1][mA[1]] = pack2(aR1.z, aR1.w);
            Bp[nxt][(kcB >> 1) + 0][nB] = pack2(bR.x, bR.y);
            Bp[nxt][(kcB >> 1) + 1][nB] = pack2(bR.z, bR.w);
        }
        __syncthreads();
    }

    // epilogue: thread's n-set = {tx+16j}
    float bsv[4];
    #pragma unroll
    for (int j = 0; j < 4; j++) {
        int c = n0 + tx + 16 * j;
        bsv[j] = bi[c] + bh[c];
    }
    #pragma unroll
    for (int i = 0; i < 8; i++) {
        int m = m0 + ty * 8 + i;
        float* op = &g_xproj[dir][m][n0];
        #pragma unroll
        for (int j = 0; j < 4; j++)
            op[tx + 16 * j] = hsum2(acc[i][j]) + bsv[j];
    }
}

// ---------------- cluster-parallel recurrent kernel (R5, verbatim) -------
// 16 clusters x 8 CTAs. Cluster = (dir, batch group of 4). CTA rank owns
// h-indices [32r, 32r+32) (all 4 gates): Whh slice (128 rows x 256) in smem.
// Per step: packed-f32x2 dots, block-local gate update, h pushed to all 8
// CTAs' smem via st.shared::cluster, one barrier.cluster.
__global__ void __launch_bounds__(256, 1) __cluster_dims__(8, 1, 1)
rec_kernel(int layer,
           const float* __restrict__ Whf, const float* __restrict__ Whb,
           const float* __restrict__ mask, float* __restrict__ dout)
{
    extern __shared__ float sm[];
    float* w_sh   = sm;              // [128][WST]
    float* h_base = sm + 128 * WST;  // [2][4][HST]
    float* part   = h_base + 8 * HST;// [8][4][4][32]

    const int bx   = blockIdx.x;
    const int cid  = bx >> 3;
    const int rank = bx & 7;
    const int dir  = cid & 1;
    const int bg4  = (cid >> 1) * 4;         // first batch of this cluster
    const int tid  = threadIdx.x;
    const float* Whh = dir ? Whb : Whf;

    // persistent weight load: local row r = g*32+jl -> Whh row g*256+rank*32+jl
    for (int i = tid; i < 128 * 64; i += 256) {
        int r  = i >> 6;
        int kk = (i & 63) << 2;
        int g = r >> 5, jl = r & 31;
        *(float4*)&w_sh[r * WST + kk] =
            *(const float4*)&Whh[((size_t)(g * 256 + rank * 32 + jl)) * 256 + kk];
    }
    // zero h buffer 0
    for (int i = tid; i < 4 * HST; i += 256) h_base[i] = 0.f;

    // compute-role mapping: warp = k-slice (32 k), lane = j-local
    const int kq   = tid >> 5;
    const int lane = tid & 31;
    const int k0   = kq * 32;

    // update-role (tid<128): b = tid>>5 (0..3), jl = tid&31
    const int ub = tid >> 5, ujl = tid & 31;
    const int bglobal = bg4 + ub;
    const int jglob = rank * 32 + ujl;
    float c_reg = 0.f;

    // prefetch step-0 xproj + mask
    float xp[4]; float mt = 0.f;
    if (tid < 128) {
        const int s0 = dir ? (SS - 1) : 0;
        const float* xb = &g_xproj[dir][(size_t)(s0 * 32 + bglobal)][jglob];
        #pragma unroll
        for (int g = 0; g < 4; g++) xp[g] = __ldcs(xb + g * 256);
        mt = mask[bglobal * SS + s0];
    }
    __syncthreads();

    int p = 0;
    for (int t = 0; t < SS; t++) {
        const int s = dir ? (SS - 1 - t) : t;
        const float* hb = h_base + p * 4 * HST;

        // packed dots: acc[g][b] over this warp's 32-k slice
        unsigned long long acc[4][4];
        #pragma unroll
        for (int g = 0; g < 4; g++)
            #pragma unroll
            for (int b = 0; b < 4; b++) acc[g][b] = 0ull;

        #pragma unroll
        for (int it = 0; it < 8; it++) {
            int kk = k0 + it * 4;
            ulonglong2 h2[4];
            #pragma unroll
            for (int b = 0; b < 4; b++)
                h2[b] = *(const ulonglong2*)&hb[b * HST + kk];
            #pragma unroll
            for (int g = 0; g < 4; g++) {
                ulonglong2 w2 = *(const ulonglong2*)&w_sh[(g * 32 + lane) * WST + kk];
                #pragma unroll
                for (int b = 0; b < 4; b++) {
                    fma2(acc[g][b], h2[b].x, w2.x);
                    fma2(acc[g][b], h2[b].y, w2.y);
                }
            }
        }
        #pragma unroll
        for (int g = 0; g < 4; g++)
            #pragma unroll
            for (int b = 0; b < 4; b++)
                part[(((kq * 4 + g) * 4 + b) * 32) + lane] = hsum2(acc[g][b]);
        __syncthreads();

        // gate combine + state update + h push
        if (tid < 128) {
            float gv[4];
            #pragma unroll
            for (int g = 0; g < 4; g++) {
                float sv = xp[g];
                #pragma unroll
                for (int q = 0; q < 8; q++)
                    sv += part[(((q * 4 + g) * 4 + ub) * 32) + ujl];
                gv[g] = sv;
            }
            float iv = sigf(gv[0]);
            float fv = sigf(gv[1]);
            float gg = tanhf(gv[2]);
            float ov = sigf(gv[3]);
            float c = (fv * c_reg + iv * gg) * mt;     // c0 = 0
            float h = ov * tanhf(c) * mt;              // h0 = 0
            c_reg = c;

            // push h into next buffer of all 8 CTAs (incl. self)
            float* hn = h_base + (p ^ 1) * 4 * HST + ub * HST + jglob;
            uint32_t laddr = smem_u32(hn);
            #pragma unroll
            for (int rk = 0; rk < 8; rk++) st_cluster_f32(laddr, rk, h);

            // sequence output
            if (layer == 0)
                g_out0[s * 32 + bglobal][dir * 256 + jglob] = h;
            else
                dout[((size_t)bglobal * SS + s) * 512 + dir * 256 + jglob] = h;
            if (t == SS - 1) {
                size_t off = (size_t)layer * BB * 512 + (size_t)bglobal * 512
                           + dir * 256 + jglob;
                dout[HN_OFF + off] = h;
                dout[CN_OFF + off] = c;
            }

            // prefetch next step's xproj + mask
            if (t + 1 < SS) {
                const int sn = dir ? (SS - 2 - t) : (t + 1);
                const float* xb = &g_xproj[dir][(size_t)(sn * 32 + bglobal)][jglob];
                #pragma unroll
                for (int g = 0; g < 4; g++) xp[g] = __ldcs(xb + g * 256);
                mt = mask[bglobal * SS + sn];
            }
        }

        // cluster barrier: release DSMEM pushes, acquire peers' pushes.
        asm volatile("barrier.cluster.arrive.aligned;" ::: "memory");
        asm volatile("barrier.cluster.wait.aligned;"   ::: "memory");
        p ^= 1;
    }
}

// ---------------- launch ------------------------------------------------
extern "C" void kernel_launch(void* const* d_in, const int* in_sizes, int n_in,
                              void* d_out, int out_size)
{
    const float* inputs  = (const float*)d_in[0];
    const float* mask    = (const float*)d_in[1];
    const float* l0f_Wih = (const float*)d_in[2];
    const float* l0f_Whh = (const float*)d_in[3];
    const float* l0f_bih = (const float*)d_in[4];
    const float* l0f_bhh = (const float*)d_in[5];
    const float* l0b_Wih = (const float*)d_in[6];
    const float* l0b_Whh = (const float*)d_in[7];
    const float* l0b_bih = (const float*)d_in[8];
    const float* l0b_bhh = (const float*)d_in[9];
    const float* l1f_Wih = (const float*)d_in[10];
    const float* l1f_Whh = (const float*)d_in[11];
    const float* l1f_bih = (const float*)d_in[12];
    const float* l1f_bhh = (const float*)d_in[13];
    const float* l1b_Wih = (const float*)d_in[14];
    const float* l1b_Whh = (const float*)d_in[15];
    const float* l1b_bih = (const float*)d_in[16];
    const float* l1b_bhh = (const float*)d_in[17];
    float* out = (float*)d_out;

    // rec dynamic smem: weights 128*260 + h 2*4*260 + partials 8*4*4*32 floats
    const int shmem = (128 * WST + 8 * HST + 8 * 4 * 4 * 32) * 4;  // 157824 B
    cudaFuncSetAttribute(rec_kernel,
                         cudaFuncAttributeMaxDynamicSharedMemorySize, shmem);

    dim3 g(16, 256, 2);   // N/64, M/128, dirs
    xproj_kernel<<<g, 256>>>(inputs, 0, 256,
                             l0f_Wih, l0b_Wih, l0f_bih, l0f_bhh, l0b_bih, l0b_bhh);
    rec_kernel<<<128, 256, shmem>>>(0, l0f_Whh, l0b_Whh, mask, out);

    xproj_kernel<<<g, 256>>>(nullptr, 1, 512,
                             l1f_Wih, l1b_Wih, l1f_bih, l1f_bhh, l1b_bih, l1b_bhh);
    rec_kernel<<<128, 256, shmem>>>(1, l1f_Whh, l1b_Whh, mask, out);
}

// round 14
// speedup vs baseline: 1.1585x; 1.1263x over previous
#include <cuda_runtime.h>
#include <cuda_bf16.h>
#include <cstdint>
#include <cstddef>

#define BB   32
#define SS   1024
#define HH   256
#define G4   1024          // 4*H
#define WST  260           // rec w_sh row stride (floats)
#define HST  260           // rec h_sh row stride

#define HN_OFF (32ull*1024ull*512ull)            // 16777216
#define CN_OFF (HN_OFF + 2ull*32ull*512ull)      // +32768

// ---------------- device scratch (no cudaMalloc allowed) ----------------
__device__ float g_xproj[2][SS*BB][G4];           // [dir][m][gate]  268MB
__device__ float g_out0[SS*BB][512];              // layer0 output
__device__ __nv_bfloat16 g_xh[SS*BB][512];        // X hi (bf16)
__device__ __nv_bfloat16 g_xl[SS*BB][512];        // X lo (bf16)
__device__ __nv_bfloat16 g_wh[2][1024][512];      // W hi per dir
__device__ __nv_bfloat16 g_wl[2][1024][512];      // W lo per dir

// ---------------- generic helpers ---------------------------------------
__device__ __forceinline__ void fma2(unsigned long long &d,
                                     unsigned long long a,
                                     unsigned long long b) {
    asm("fma.rn.f32x2 %0, %1, %2, %0;" : "+l"(d) : "l"(a), "l"(b));
}
__device__ __forceinline__ float hsum2(unsigned long long v) {
    return __uint_as_float((unsigned)v) + __uint_as_float((unsigned)(v >> 32));
}
__device__ __forceinline__ float sigf(float x) { return 1.f / (1.f + expf(-x)); }

__device__ __forceinline__ uint32_t smem_u32(const void* p) {
    return (uint32_t)__cvta_generic_to_shared(p);
}
__device__ __forceinline__ void st_cluster_f32(uint32_t laddr, uint32_t rk, float v) {
    uint32_t ra;
    asm volatile("mapa.shared::cluster.u32 %0, %1, %2;"
                 : "=r"(ra) : "r"(laddr), "r"(rk));
    asm volatile("st.shared::cluster.f32 [%0], %1;"
                 :: "r"(ra), "f"(v) : "memory");
}
__device__ __forceinline__ uint32_t lds32(const __nv_bfloat16* p) {
    return *(const uint32_t*)p;
}
__device__ __forceinline__ void mma_bf16(float* c, const uint32_t* a,
                                         const uint32_t* b) {
    asm volatile(
        "mma.sync.aligned.m16n8k16.row.col.f32.bf16.bf16.f32 "
        "{%0,%1,%2,%3}, {%4,%5,%6,%7}, {%8,%9}, {%0,%1,%2,%3};"
        : "+f"(c[0]), "+f"(c[1]), "+f"(c[2]), "+f"(c[3])
        : "r"(a[0]), "r"(a[1]), "r"(a[2]), "r"(a[3]), "r"(b[0]), "r"(b[1]));
}

// ---------------- split kernels: fp32 -> bf16 hi/lo ----------------------
__global__ void split_x_kernel(const float* __restrict__ xin, int layer, int K) {
    const int m = blockIdx.x;
    const int k = threadIdx.x << 2;
    const float* src;
    if (layer == 0) {
        int s = m >> 5, b = m & 31;
        src = xin + ((size_t)b * SS + s) * 256 + k;
    } else {
        src = &g_out0[m][k];
    }
    float4 v = *(const float4*)src;
    float vv[4] = {v.x, v.y, v.z, v.w};
    __nv_bfloat16 hh[4], ll[4];
    #pragma unroll
    for (int i = 0; i < 4; i++) {
        hh[i] = __float2bfloat16(vv[i]);
        ll[i] = __float2bfloat16(vv[i] - __bfloat162float(hh[i]));
    }
    __nv_bfloat162 p0, p1;
    p0.x = hh[0]; p0.y = hh[1]; p1.x = hh[2]; p1.y = hh[3];
    *(__nv_bfloat162*)&g_xh[m][k]     = p0;
    *(__nv_bfloat162*)&g_xh[m][k + 2] = p1;
    p0.x = ll[0]; p0.y = ll[1]; p1.x = ll[2]; p1.y = ll[3];
    *(__nv_bfloat162*)&g_xl[m][k]     = p0;
    *(__nv_bfloat162*)&g_xl[m][k + 2] = p1;
}

__global__ void split_w_kernel(const float* __restrict__ Wf,
                               const float* __restrict__ Wb, int K) {
    const int n = blockIdx.x;
    const int dir = blockIdx.y;
    const int k = threadIdx.x << 2;
    const float* W = dir ? Wb : Wf;
    float4 v = *(const float4*)(W + (size_t)n * K + k);
    float vv[4] = {v.x, v.y, v.z, v.w};
    __nv_bfloat16 hh[4], ll[4];
    #pragma unroll
    for (int i = 0; i < 4; i++) {
        hh[i] = __float2bfloat16(vv[i]);
        ll[i] = __float2bfloat16(vv[i] - __bfloat162float(hh[i]));
    }
    __nv_bfloat162 p0, p1;
    p0.x = hh[0]; p0.y = hh[1]; p1.x = hh[2]; p1.y = hh[3];
    *(__nv_bfloat162*)&g_wh[dir][n][k]     = p0;
    *(__nv_bfloat162*)&g_wh[dir][n][k + 2] = p1;
    p0.x = ll[0]; p0.y = ll[1]; p1.x = ll[2]; p1.y = ll[3];
    *(__nv_bfloat162*)&g_wl[dir][n][k]     = p0;
    *(__nv_bfloat162*)&g_wl[dir][n][k + 2] = p1;
}

// ---------------- mma.sync xproj GEMM ------------------------------------
// C[m][n] = sum_k X[m][k]*W[n][k]; bf16 split (hh + hl + lh), fp32 acc.
// BM=128, BN=64, K-chunk 32; 8 warps: warp tile 32(m) x 32(n) = 2 x 4 mma
// tiles of m16n8k16. Smem rows padded to 40 bf16 (80B = 5*16B).
#define KC   32
#define ASTR2 40
__global__ void __launch_bounds__(256, 2) mma_xproj_kernel(
    int NC, const float* __restrict__ bif, const float* __restrict__ bhf,
    const float* __restrict__ bib, const float* __restrict__ bhb)
{
    __shared__ __align__(16) __nv_bfloat16 smA[2][128][ASTR2];
    __shared__ __align__(16) __nv_bfloat16 smB[2][64][ASTR2];

    const int tid = threadIdx.x;
    const int wid = tid >> 5, lane = tid & 31;
    const int wm = wid & 3, wn = wid >> 2;          // warp tile coords
    const int g = lane >> 2, t = lane & 3;          // fragment coords
    const int n0 = blockIdx.x * 64, m0 = blockIdx.y * 128, dir = blockIdx.z;
    const float* bi  = dir ? bib : bif;
    const float* bhv = dir ? bhb : bhf;

    // staging roles: A 4 float4 slots, B 2 float4 slots per thread
    int aRow[4], aF4[4], aHL[4];
    #pragma unroll
    for (int i = 0; i < 4; i++) {
        int idx = tid + (i << 8);
        aF4[i]  = idx & 3;
        aRow[i] = (idx >> 2) & 127;
        aHL[i]  = idx >> 9;
    }
    int bRow[2], bF4[2], bHL[2];
    #pragma unroll
    for (int i = 0; i < 2; i++) {
        int idx = tid + (i << 8);
        bF4[i]  = idx & 3;
        bRow[i] = (idx >> 2) & 63;
        bHL[i]  = idx >> 8;
    }

    float acc[2][4][4];
    #pragma unroll
    for (int mt = 0; mt < 2; mt++)
        #pragma unroll
        for (int nt = 0; nt < 4; nt++)
            #pragma unroll
            for (int e = 0; e < 4; e++) acc[mt][nt][e] = 0.f;

    // prologue: stage chunk 0
    float4 aReg[4], bReg[2];
    #pragma unroll
    for (int i = 0; i < 4; i++)
        aReg[i] = *(const float4*)((aHL[i] ? &g_xl[0][0] : &g_xh[0][0])
                    + (size_t)(m0 + aRow[i]) * 512 + aF4[i] * 8);
    #pragma unroll
    for (int i = 0; i < 2; i++)
        bReg[i] = *(const float4*)((bHL[i] ? &g_wl[dir][0][0] : &g_wh[dir][0][0])
                    + (size_t)(n0 + bRow[i]) * 512 + bF4[i] * 8);
    #pragma unroll
    for (int i = 0; i < 4; i++)
        *(float4*)&smA[aHL[i]][aRow[i]][aF4[i] * 8] = aReg[i];
    #pragma unroll
    for (int i = 0; i < 2; i++)
        *(float4*)&smB[bHL[i]][bRow[i]][bF4[i] * 8] = bReg[i];
    __syncthreads();

    for (int c = 0; c < NC; c++) {
        const bool more = (c + 1 < NC);
        if (more) {
            const int kb = (c + 1) * KC;
            #pragma unroll
            for (int i = 0; i < 4; i++)
                aReg[i] = *(const float4*)((aHL[i] ? &g_xl[0][0] : &g_xh[0][0])
                            + (size_t)(m0 + aRow[i]) * 512 + kb + aF4[i] * 8);
            #pragma unroll
            for (int i = 0; i < 2; i++)
                bReg[i] = *(const float4*)((bHL[i] ? &g_wl[dir][0][0] : &g_wh[dir][0][0])
                            + (size_t)(n0 + bRow[i]) * 512 + kb + bF4[i] * 8);
        }
        // compute: two k16 steps
        #pragma unroll
        for (int ks = 0; ks < 2; ks++) {
            const int kk = ks * 16;
            uint32_t ah[2][4], al[2][4], bh[4][2], bl[4][2];
            #pragma unroll
            for (int mt = 0; mt < 2; mt++) {
                const int r0 = wm * 32 + mt * 16 + g;
                ah[mt][0] = lds32(&smA[0][r0    ][kk + 2*t]);
                ah[mt][1] = lds32(&smA[0][r0 + 8][kk + 2*t]);
                ah[mt][2] = lds32(&smA[0][r0    ][kk + 2*t + 8]);
                ah[mt][3] = lds32(&smA[0][r0 + 8][kk + 2*t + 8]);
                al[mt][0] = lds32(&smA[1][r0    ][kk + 2*t]);
                al[mt][1] = lds32(&smA[1][r0 + 8][kk + 2*t]);
                al[mt][2] = lds32(&smA[1][r0    ][kk + 2*t + 8]);
                al[mt][3] = lds32(&smA[1][r0 + 8][kk + 2*t + 8]);
            }
            #pragma unroll
            for (int nt = 0; nt < 4; nt++) {
                const int rn = wn * 32 + nt * 8 + g;
                bh[nt][0] = lds32(&smB[0][rn][kk + 2*t]);
                bh[nt][1] = lds32(&smB[0][rn][kk + 2*t + 8]);
                bl[nt][0] = lds32(&smB[1][rn][kk + 2*t]);
                bl[nt][1] = lds32(&smB[1][rn][kk + 2*t + 8]);
            }
            #pragma unroll
            for (int mt = 0; mt < 2; mt++)
                #pragma unroll
                for (int nt = 0; nt < 4; nt++) {
                    mma_bf16(acc[mt][nt], ah[mt], bh[nt]);
                    mma_bf16(acc[mt][nt], ah[mt], bl[nt]);
                    mma_bf16(acc[mt][nt], al[mt], bh[nt]);
                }
        }
        __syncthreads();
        if (more) {
            #pragma unroll
            for (int i = 0; i < 4; i++)
                *(float4*)&smA[aHL[i]][aRow[i]][aF4[i] * 8] = aReg[i];
            #pragma unroll
            for (int i = 0; i < 2; i++)
                *(float4*)&smB[bHL[i]][bRow[i]][bF4[i] * 8] = bReg[i];
            __syncthreads();
        }
    }

    // epilogue: acc -> g_xproj with biases
    #pragma unroll
    for (int mt = 0; mt < 2; mt++) {
        const int m = m0 + wm * 32 + mt * 16 + g;
        #pragma unroll
        for (int nt = 0; nt < 4; nt++) {
            const int n = n0 + wn * 32 + nt * 8 + 2 * t;
            const float b0 = bi[n]     + bhv[n];
            const float b1 = bi[n + 1] + bhv[n + 1];
            float2 lo, hi;
            lo.x = acc[mt][nt][0] + b0; lo.y = acc[mt][nt][1] + b1;
            hi.x = acc[mt][nt][2] + b0; hi.y = acc[mt][nt][3] + b1;
            *(float2*)&g_xproj[dir][m][n]     = lo;
            *(float2*)&g_xproj[dir][m + 8][n] = hi;
        }
    }
}

// ---------------- cluster-parallel recurrent kernel (R5, verbatim) -------
__global__ void __launch_bounds__(256, 1) __cluster_dims__(8, 1, 1)
rec_kernel(int layer,
           const float* __restrict__ Whf, const float* __restrict__ Whb,
           const float* __restrict__ mask, float* __restrict__ dout)
{
    extern __shared__ float sm[];
    float* w_sh   = sm;              // [128][WST]
    float* h_base = sm + 128 * WST;  // [2][4][HST]
    float* part   = h_base + 8 * HST;// [8][4][4][32]

    const int bx   = blockIdx.x;
    const int cid  = bx >> 3;
    const int rank = bx & 7;
    const int dir  = cid & 1;
    const int bg4  = (cid >> 1) * 4;
    const int tid  = threadIdx.x;
    const float* Whh = dir ? Whb : Whf;

    for (int i = tid; i < 128 * 64; i += 256) {
        int r  = i >> 6;
        int kk = (i & 63) << 2;
        int g = r >> 5, jl = r & 31;
        *(float4*)&w_sh[r * WST + kk] =
            *(const float4*)&Whh[((size_t)(g * 256 + rank * 32 + jl)) * 256 + kk];
    }
    for (int i = tid; i < 4 * HST; i += 256) h_base[i] = 0.f;

    const int kq   = tid >> 5;
    const int lane = tid & 31;
    const int k0   = kq * 32;

    const int ub = tid >> 5, ujl = tid & 31;
    const int bglobal = bg4 + ub;
    const int jglob = rank * 32 + ujl;
    float c_reg = 0.f;

    float xp[4]; float mt = 0.f;
    if (tid < 128) {
        const int s0 = dir ? (SS - 1) : 0;
        const float* xb = &g_xproj[dir][(size_t)(s0 * 32 + bglobal)][jglob];
        #pragma unroll
        for (int g = 0; g < 4; g++) xp[g] = __ldcs(xb + g * 256);
        mt = mask[bglobal * SS + s0];
    }
    __syncthreads();

    int p = 0;
    for (int t = 0; t < SS; t++) {
        const int s = dir ? (SS - 1 - t) : t;
        const float* hb = h_base + p * 4 * HST;

        unsigned long long acc[4][4];
        #pragma unroll
        for (int g = 0; g < 4; g++)
            #pragma unroll
            for (int b = 0; b < 4; b++) acc[g][b] = 0ull;

        #pragma unroll
        for (int it = 0; it < 8; it++) {
            int kk = k0 + it * 4;
            ulonglong2 h2[4];
            #pragma unroll
            for (int b = 0; b < 4; b++)
                h2[b] = *(const ulonglong2*)&hb[b * HST + kk];
            #pragma unroll
            for (int g = 0; g < 4; g++) {
                ulonglong2 w2 = *(const ulonglong2*)&w_sh[(g * 32 + lane) * WST + kk];
                #pragma unroll
                for (int b = 0; b < 4; b++) {
                    fma2(acc[g][b], h2[b].x, w2.x);
                    fma2(acc[g][b], h2[b].y, w2.y);
                }
            }
        }
        #pragma unroll
        for (int g = 0; g < 4; g++)
            #pragma unroll
            for (int b = 0; b < 4; b++)
                part[(((kq * 4 + g) * 4 + b) * 32) + lane] = hsum2(acc[g][b]);
        __syncthreads();

        if (tid < 128) {
            float gv[4];
            #pragma unroll
            for (int g = 0; g < 4; g++) {
                float sv = xp[g];
                #pragma unroll
                for (int q = 0; q < 8; q++)
                    sv += part[(((q * 4 + g) * 4 + ub) * 32) + ujl];
                gv[g] = sv;
            }
            float iv = sigf(gv[0]);
            float fv = sigf(gv[1]);
            float gg = tanhf(gv[2]);
            float ov = sigf(gv[3]);
            float c = (fv * c_reg + iv * gg) * mt;
            float h = ov * tanhf(c) * mt;
            c_reg = c;

            float* hn = h_base + (p ^ 1) * 4 * HST + ub * HST + jglob;
            uint32_t laddr = smem_u32(hn);
            #pragma unroll
            for (int rk = 0; rk < 8; rk++) st_cluster_f32(laddr, rk, h);

            if (layer == 0)
                g_out0[s * 32 + bglobal][dir * 256 + jglob] = h;
            else
                dout[((size_t)bglobal * SS + s) * 512 + dir * 256 + jglob] = h;
            if (t == SS - 1) {
                size_t off = (size_t)layer * BB * 512 + (size_t)bglobal * 512
                           + dir * 256 + jglob;
                dout[HN_OFF + off] = h;
                dout[CN_OFF + off] = c;
            }

            if (t + 1 < SS) {
                const int sn = dir ? (SS - 2 - t) : (t + 1);
                const float* xb = &g_xproj[dir][(size_t)(sn * 32 + bglobal)][jglob];
                #pragma unroll
                for (int g = 0; g < 4; g++) xp[g] = __ldcs(xb + g * 256);
                mt = mask[bglobal * SS + sn];
            }
        }

        asm volatile("barrier.cluster.arrive.aligned;" ::: "memory");
        asm volatile("barrier.cluster.wait.aligned;"   ::: "memory");
        p ^= 1;
    }
}

// ---------------- launch ------------------------------------------------
extern "C" void kernel_launch(void* const* d_in, const int* in_sizes, int n_in,
                              void* d_out, int out_size)
{
    const float* inputs  = (const float*)d_in[0];
    const float* mask    = (const float*)d_in[1];
    const float* l0f_Wih = (const float*)d_in[2];
    const float* l0f_Whh = (const float*)d_in[3];
    const float* l0f_bih = (const float*)d_in[4];
    const float* l0f_bhh = (const float*)d_in[5];
    const float* l0b_Wih = (const float*)d_in[6];
    const float* l0b_Whh = (const float*)d_in[7];
    const float* l0b_bih = (const float*)d_in[8];
    const float* l0b_bhh = (const float*)d_in[9];
    const float* l1f_Wih = (const float*)d_in[10];
    const float* l1f_Whh = (const float*)d_in[11];
    const float* l1f_bih = (const float*)d_in[12];
    const float* l1f_bhh = (const float*)d_in[13];
    const float* l1b_Wih = (const float*)d_in[14];
    const float* l1b_Whh = (const float*)d_in[15];
    const float* l1b_bih = (const float*)d_in[16];
    const float* l1b_bhh = (const float*)d_in[17];
    float* out = (float*)d_out;

    const int rec_shmem = (128 * WST + 8 * HST + 8 * 4 * 4 * 32) * 4;  // 157824
    cudaFuncSetAttribute(rec_kernel,
                         cudaFuncAttributeMaxDynamicSharedMemorySize, rec_shmem);

    dim3 gm(16, 256, 2);   // n-tiles, m-tiles, dirs

    // ---- layer 0 (K = 256 -> 8 chunks) ----
    split_x_kernel<<<SS * BB, 64>>>(inputs, 0, 256);
    split_w_kernel<<<dim3(1024, 2), 64>>>(l0f_Wih, l0b_Wih, 256);
    mma_xproj_kernel<<<gm, 256>>>(8, l0f_bih, l0f_bhh, l0b_bih, l0b_bhh);
    rec_kernel<<<128, 256, rec_shmem>>>(0, l0f_Whh, l0b_Whh, mask, out);

    // ---- layer 1 (K = 512 -> 16 chunks) ----
    split_x_kernel<<<SS * BB, 128>>>(nullptr, 1, 512);
    split_w_kernel<<<dim3(1024, 2), 128>>>(l1f_Wih, l1b_Wih, 512);
    mma_xproj_kernel<<<gm, 256>>>(16, l1f_bih, l1f_bhh, l1b_bih, l1b_bhh);
    rec_kernel<<<128, 256, rec_shmem>>>(1, l1f_Whh, l1b_Whh, mask, out);
}